// round 2
// baseline (speedup 1.0000x reference)
#include <cuda_runtime.h>
#include <math.h>

#define SS 512
#define BB 64
#define II 1024
#define HH 1024
#define G4 4096   // 4*H

// Scratch: xW for all timesteps (fp32), and ping-pong cell state.
__device__ float g_xw[(size_t)SS * BB * G4];   // 512 MB
__device__ float g_c[2][BB * HH];

__device__ __forceinline__ float sigf(float x) {
    return 1.0f / (1.0f + __expf(-x));
}

// ---------------------------------------------------------------------------
// Kernel A: g_xw[m, g] = sum_i X[m, i] * W[g, i] + bias[g]
//   X: [32768, 1024] row-major (s*B+b major), W: [4096, 1024] row-major.
//   Tile: BM=64, BN=64, BK=32, 256 threads, 4x4 per thread.
// ---------------------------------------------------------------------------
__global__ __launch_bounds__(256) void gemm_xw(const float* __restrict__ X,
                                               const float* __restrict__ W,
                                               const float* __restrict__ bias) {
    __shared__ __align__(16) float As[32][68];   // [k][m], pad 4 for banks + f4 align
    __shared__ __align__(16) float Bs[32][68];   // [k][n]

    const int m0 = blockIdx.y * 64;
    const int n0 = blockIdx.x * 64;
    const int tid = threadIdx.x;
    const int tx = tid & 15;          // 0..15 -> n
    const int ty = tid >> 4;          // 0..15 -> m
    const int r  = tid >> 3;          // 0..31  loader row
    const int kv = (tid & 7) << 2;    // 0,4,...,28

    float acc[4][4] = {};

    for (int k0 = 0; k0 < II; k0 += 32) {
        float4 a0 = *(const float4*)(X + (size_t)(m0 + r)      * II + k0 + kv);
        float4 a1 = *(const float4*)(X + (size_t)(m0 + r + 32) * II + k0 + kv);
        float4 b0 = *(const float4*)(W + (size_t)(n0 + r)      * II + k0 + kv);
        float4 b1 = *(const float4*)(W + (size_t)(n0 + r + 32) * II + k0 + kv);

        As[kv+0][r] = a0.x; As[kv+1][r] = a0.y; As[kv+2][r] = a0.z; As[kv+3][r] = a0.w;
        As[kv+0][r+32] = a1.x; As[kv+1][r+32] = a1.y; As[kv+2][r+32] = a1.z; As[kv+3][r+32] = a1.w;
        Bs[kv+0][r] = b0.x; Bs[kv+1][r] = b0.y; Bs[kv+2][r] = b0.z; Bs[kv+3][r] = b0.w;
        Bs[kv+0][r+32] = b1.x; Bs[kv+1][r+32] = b1.y; Bs[kv+2][r+32] = b1.z; Bs[kv+3][r+32] = b1.w;
        __syncthreads();

        #pragma unroll
        for (int k = 0; k < 32; k++) {
            float4 av = *(const float4*)&As[k][ty << 2];
            float4 bv = *(const float4*)&Bs[k][tx << 2];
            float am[4] = {av.x, av.y, av.z, av.w};
            float bn[4] = {bv.x, bv.y, bv.z, bv.w};
            #pragma unroll
            for (int i = 0; i < 4; i++)
                #pragma unroll
                for (int j = 0; j < 4; j++)
                    acc[i][j] += am[i] * bn[j];
        }
        __syncthreads();
    }

    const int nn = n0 + (tx << 2);
    float4 bsv = *(const float4*)(bias + nn);
    float bb4[4] = {bsv.x, bsv.y, bsv.z, bsv.w};
    #pragma unroll
    for (int i = 0; i < 4; i++) {
        const int m = m0 + (ty << 2) + i;
        float4 ov;
        ov.x = acc[i][0] + bb4[0];
        ov.y = acc[i][1] + bb4[1];
        ov.z = acc[i][2] + bb4[2];
        ov.w = acc[i][3] + bb4[3];
        *(float4*)(g_xw + (size_t)m * G4 + nn) = ov;
    }
}

// ---------------------------------------------------------------------------
// Kernel B: one LSTM step, fused GEMM + gates.
//   gates[b, g] = g_xw[t, b, g] + sum_k h_prev[b, k] * U[g, k]
//   Block (nb, mb): batch rows [mb*32, mb*32+32), gate-local cols
//   [nb*16, nb*16+16) for each of the 4 gates -> 64 output columns
//   c = nb*16*... mapping: c in [0,64), G = (c/16)*H + nb*16 + (c%16).
//   128 threads, 4x4 per thread. Elementwise fused via smem gate buffer.
// ---------------------------------------------------------------------------
__global__ __launch_bounds__(128) void lstm_step(const float* __restrict__ hprev,
                                                 const float* __restrict__ U,
                                                 int t, int par,
                                                 float* __restrict__ hout) {
    __shared__ __align__(16) float Hs[32][36];   // [k][m]
    __shared__ __align__(16) float Us[32][68];   // [k][c]
    __shared__ float gbuf[32][68];

    const int nb = blockIdx.x;            // 0..63
    const int m0 = blockIdx.y << 5;       // 0 or 32
    const int tid = threadIdx.x;          // 128
    const int tx = tid & 15;              // 0..15 -> c group
    const int ty = tid >> 4;              // 0..7  -> m group

    // Loader indices
    const int hr = tid >> 3;              // 0..15
    const int hk = (tid & 7) << 2;        // 0..28
    const int uc = tid >> 1;              // 0..63
    const int ukb = (tid & 1) << 2;       // 0 or 4
    const int uG = ((uc >> 4) << 10) + (nb << 4) + (uc & 15);
    const float* Urow = U + (size_t)uG * HH;

    float acc[4][4] = {};

    for (int k0 = 0; k0 < HH; k0 += 32) {
        float4 h0v = *(const float4*)(hprev + (size_t)(m0 + hr)      * HH + k0 + hk);
        float4 h1v = *(const float4*)(hprev + (size_t)(m0 + hr + 16) * HH + k0 + hk);
        Hs[hk+0][hr] = h0v.x; Hs[hk+1][hr] = h0v.y; Hs[hk+2][hr] = h0v.z; Hs[hk+3][hr] = h0v.w;
        Hs[hk+0][hr+16] = h1v.x; Hs[hk+1][hr+16] = h1v.y; Hs[hk+2][hr+16] = h1v.z; Hs[hk+3][hr+16] = h1v.w;

        #pragma unroll
        for (int q = 0; q < 4; q++) {
            const int kk = ukb + (q << 3);
            float4 uv = *(const float4*)(Urow + k0 + kk);
            Us[kk+0][uc] = uv.x; Us[kk+1][uc] = uv.y;
            Us[kk+2][uc] = uv.z; Us[kk+3][uc] = uv.w;
        }
        __syncthreads();

        #pragma unroll
        for (int k = 0; k < 32; k++) {
            float4 av = *(const float4*)&Hs[k][ty << 2];
            float4 bv = *(const float4*)&Us[k][tx << 2];
            float am[4] = {av.x, av.y, av.z, av.w};
            float bn[4] = {bv.x, bv.y, bv.z, bv.w};
            #pragma unroll
            for (int i = 0; i < 4; i++)
                #pragma unroll
                for (int j = 0; j < 4; j++)
                    acc[i][j] += am[i] * bn[j];
        }
        __syncthreads();
    }

    // Add xW contribution, stage gates in smem.
    #pragma unroll
    for (int i = 0; i < 4; i++) {
        const int m = (ty << 2) + i;
        #pragma unroll
        for (int j = 0; j < 4; j++) {
            const int c = (tx << 2) + j;
            const int Gc = ((c >> 4) << 10) + (nb << 4) + (c & 15);
            gbuf[m][c] = acc[i][j] +
                g_xw[((size_t)t * BB + m0 + m) * G4 + Gc];
        }
    }
    __syncthreads();

    // Fused elementwise: 32 rows x 16 j = 512 items / 128 threads = 4 each.
    const float* cprev = g_c[par];
    float* cout = g_c[par ^ 1];
    #pragma unroll
    for (int q = 0; q < 4; q++) {
        const int p = tid + (q << 7);     // 0..511
        const int bm = p >> 4;            // 0..31
        const int jj = p & 15;
        const float iv = sigf(gbuf[bm][jj]);
        const float fv = sigf(gbuf[bm][16 + jj]);
        const float gv = tanhf(gbuf[bm][32 + jj]);
        const float ov = sigf(gbuf[bm][48 + jj]);
        const int idx = (m0 + bm) * HH + (nb << 4) + jj;
        const float cn = fv * cprev[idx] + iv * gv;
        cout[idx] = cn;
        hout[idx] = ov * tanhf(cn);
    }
}

// ---------------------------------------------------------------------------
// Small helpers: seed c buffer, emit h_t / c_t tails.
// ---------------------------------------------------------------------------
__global__ void copy_c0(const float* __restrict__ c0) {
    const int i = blockIdx.x * 256 + threadIdx.x;
    g_c[0][i] = c0[i];
}

__global__ void finalize(float* __restrict__ out) {
    const int i = blockIdx.x * 256 + threadIdx.x;
    const size_t base = (size_t)SS * BB * HH;
    out[base + i] = out[(size_t)(SS - 1) * BB * HH + i];   // h_t
    out[base + BB * HH + i] = g_c[0][i];                   // c_t (S even -> final in g_c[0])
}

// ---------------------------------------------------------------------------
extern "C" void kernel_launch(void* const* d_in, const int* in_sizes, int n_in,
                              void* d_out, int out_size) {
    (void)in_sizes; (void)n_in; (void)out_size;
    const float* x  = (const float*)d_in[0];
    const float* h0 = (const float*)d_in[1];
    const float* c0 = (const float*)d_in[2];
    const float* Ww = (const float*)d_in[3];
    const float* Wb = (const float*)d_in[4];
    const float* Uw = (const float*)d_in[5];
    float* out = (float*)d_out;

    copy_c0<<<(BB * HH) / 256, 256>>>(c0);

    gemm_xw<<<dim3(G4 / 64, (SS * BB) / 64), 256>>>(x, Ww, Wb);

    for (int t = 0; t < SS; t++) {
        const float* hp = (t == 0) ? h0 : (out + (size_t)(t - 1) * BB * HH);
        lstm_step<<<dim3(HH / 16, BB / 32), 128>>>(hp, Uw, t, t & 1,
                                                   out + (size_t)t * BB * HH);
    }

    finalize<<<(BB * HH) / 256, 256>>>(out);
}

// round 3
// speedup vs baseline: 1.0004x; 1.0004x over previous
#include <cuda_runtime.h>
#include <math.h>

#define SS 512
#define BB 64
#define II 1024
#define HH 1024
#define G4 4096   // 4*H

// Scratch: xW for all timesteps (fp32), and ping-pong cell state.
__device__ float g_xw[(size_t)SS * BB * G4];   // 512 MB
__device__ float g_c[2][BB * HH];

__device__ __forceinline__ float sigf(float x) {
    return 1.0f / (1.0f + __expf(-x));
}

// ---------------------------------------------------------------------------
// Kernel A: g_xw[m, g] = sum_i X[m, i] * W[g, i] + bias[g]
//   X: [32768, 1024] row-major (s*B+b major), W: [4096, 1024] row-major.
//   Tile: BM=64, BN=64, BK=32, 256 threads, 4x4 per thread.
// ---------------------------------------------------------------------------
__global__ __launch_bounds__(256) void gemm_xw(const float* __restrict__ X,
                                               const float* __restrict__ W,
                                               const float* __restrict__ bias) {
    __shared__ __align__(16) float As[32][68];   // [k][m], pad 4 for banks + f4 align
    __shared__ __align__(16) float Bs[32][68];   // [k][n]

    const int m0 = blockIdx.y * 64;
    const int n0 = blockIdx.x * 64;
    const int tid = threadIdx.x;
    const int tx = tid & 15;          // 0..15 -> n
    const int ty = tid >> 4;          // 0..15 -> m
    const int r  = tid >> 3;          // 0..31  loader row
    const int kv = (tid & 7) << 2;    // 0,4,...,28

    float acc[4][4] = {};

    for (int k0 = 0; k0 < II; k0 += 32) {
        float4 a0 = *(const float4*)(X + (size_t)(m0 + r)      * II + k0 + kv);
        float4 a1 = *(const float4*)(X + (size_t)(m0 + r + 32) * II + k0 + kv);
        float4 b0 = *(const float4*)(W + (size_t)(n0 + r)      * II + k0 + kv);
        float4 b1 = *(const float4*)(W + (size_t)(n0 + r + 32) * II + k0 + kv);

        As[kv+0][r] = a0.x; As[kv+1][r] = a0.y; As[kv+2][r] = a0.z; As[kv+3][r] = a0.w;
        As[kv+0][r+32] = a1.x; As[kv+1][r+32] = a1.y; As[kv+2][r+32] = a1.z; As[kv+3][r+32] = a1.w;
        Bs[kv+0][r] = b0.x; Bs[kv+1][r] = b0.y; Bs[kv+2][r] = b0.z; Bs[kv+3][r] = b0.w;
        Bs[kv+0][r+32] = b1.x; Bs[kv+1][r+32] = b1.y; Bs[kv+2][r+32] = b1.z; Bs[kv+3][r+32] = b1.w;
        __syncthreads();

        #pragma unroll
        for (int k = 0; k < 32; k++) {
            float4 av = *(const float4*)&As[k][ty << 2];
            float4 bv = *(const float4*)&Bs[k][tx << 2];
            float am[4] = {av.x, av.y, av.z, av.w};
            float bn[4] = {bv.x, bv.y, bv.z, bv.w};
            #pragma unroll
            for (int i = 0; i < 4; i++)
                #pragma unroll
                for (int j = 0; j < 4; j++)
                    acc[i][j] += am[i] * bn[j];
        }
        __syncthreads();
    }

    const int nn = n0 + (tx << 2);
    float4 bsv = *(const float4*)(bias + nn);
    float bb4[4] = {bsv.x, bsv.y, bsv.z, bsv.w};
    #pragma unroll
    for (int i = 0; i < 4; i++) {
        const int m = m0 + (ty << 2) + i;
        float4 ov;
        ov.x = acc[i][0] + bb4[0];
        ov.y = acc[i][1] + bb4[1];
        ov.z = acc[i][2] + bb4[2];
        ov.w = acc[i][3] + bb4[3];
        *(float4*)(g_xw + (size_t)m * G4 + nn) = ov;
    }
}

// ---------------------------------------------------------------------------
// Kernel B: one LSTM step, fused GEMM + gates.
//   gates[b, g] = g_xw[t, b, g] + sum_k h_prev[b, k] * U[g, k]
//   Block (nb, mb): batch rows [mb*32, mb*32+32), gate-local cols
//   [nb*16, nb*16+16) for each of the 4 gates -> 64 output columns
//   c = nb*16*... mapping: c in [0,64), G = (c/16)*H + nb*16 + (c%16).
//   128 threads, 4x4 per thread. Elementwise fused via smem gate buffer.
// ---------------------------------------------------------------------------
__global__ __launch_bounds__(128) void lstm_step(const float* __restrict__ hprev,
                                                 const float* __restrict__ U,
                                                 int t, int par,
                                                 float* __restrict__ hout) {
    __shared__ __align__(16) float Hs[32][36];   // [k][m]
    __shared__ __align__(16) float Us[32][68];   // [k][c]
    __shared__ float gbuf[32][68];

    const int nb = blockIdx.x;            // 0..63
    const int m0 = blockIdx.y << 5;       // 0 or 32
    const int tid = threadIdx.x;          // 128
    const int tx = tid & 15;              // 0..15 -> c group
    const int ty = tid >> 4;              // 0..7  -> m group

    // Loader indices
    const int hr = tid >> 3;              // 0..15
    const int hk = (tid & 7) << 2;        // 0..28
    const int uc = tid >> 1;              // 0..63
    const int ukb = (tid & 1) << 2;       // 0 or 4
    const int uG = ((uc >> 4) << 10) + (nb << 4) + (uc & 15);
    const float* Urow = U + (size_t)uG * HH;

    float acc[4][4] = {};

    for (int k0 = 0; k0 < HH; k0 += 32) {
        float4 h0v = *(const float4*)(hprev + (size_t)(m0 + hr)      * HH + k0 + hk);
        float4 h1v = *(const float4*)(hprev + (size_t)(m0 + hr + 16) * HH + k0 + hk);
        Hs[hk+0][hr] = h0v.x; Hs[hk+1][hr] = h0v.y; Hs[hk+2][hr] = h0v.z; Hs[hk+3][hr] = h0v.w;
        Hs[hk+0][hr+16] = h1v.x; Hs[hk+1][hr+16] = h1v.y; Hs[hk+2][hr+16] = h1v.z; Hs[hk+3][hr+16] = h1v.w;

        #pragma unroll
        for (int q = 0; q < 4; q++) {
            const int kk = ukb + (q << 3);
            float4 uv = *(const float4*)(Urow + k0 + kk);
            Us[kk+0][uc] = uv.x; Us[kk+1][uc] = uv.y;
            Us[kk+2][uc] = uv.z; Us[kk+3][uc] = uv.w;
        }
        __syncthreads();

        #pragma unroll
        for (int k = 0; k < 32; k++) {
            float4 av = *(const float4*)&Hs[k][ty << 2];
            float4 bv = *(const float4*)&Us[k][tx << 2];
            float am[4] = {av.x, av.y, av.z, av.w};
            float bn[4] = {bv.x, bv.y, bv.z, bv.w};
            #pragma unroll
            for (int i = 0; i < 4; i++)
                #pragma unroll
                for (int j = 0; j < 4; j++)
                    acc[i][j] += am[i] * bn[j];
        }
        __syncthreads();
    }

    // Add xW contribution, stage gates in smem.
    #pragma unroll
    for (int i = 0; i < 4; i++) {
        const int m = (ty << 2) + i;
        #pragma unroll
        for (int j = 0; j < 4; j++) {
            const int c = (tx << 2) + j;
            const int Gc = ((c >> 4) << 10) + (nb << 4) + (c & 15);
            gbuf[m][c] = acc[i][j] +
                g_xw[((size_t)t * BB + m0 + m) * G4 + Gc];
        }
    }
    __syncthreads();

    // Fused elementwise: 32 rows x 16 j = 512 items / 128 threads = 4 each.
    const float* cprev = g_c[par];
    float* cout = g_c[par ^ 1];
    #pragma unroll
    for (int q = 0; q < 4; q++) {
        const int p = tid + (q << 7);     // 0..511
        const int bm = p >> 4;            // 0..31
        const int jj = p & 15;
        const float iv = sigf(gbuf[bm][jj]);
        const float fv = sigf(gbuf[bm][16 + jj]);
        const float gv = tanhf(gbuf[bm][32 + jj]);
        const float ov = sigf(gbuf[bm][48 + jj]);
        const int idx = (m0 + bm) * HH + (nb << 4) + jj;
        const float cn = fv * cprev[idx] + iv * gv;
        cout[idx] = cn;
        hout[idx] = ov * tanhf(cn);
    }
}

// ---------------------------------------------------------------------------
// Small helpers: seed c buffer, emit h_t / c_t tails.
// ---------------------------------------------------------------------------
__global__ void copy_c0(const float* __restrict__ c0) {
    const int i = blockIdx.x * 256 + threadIdx.x;
    g_c[0][i] = c0[i];
}

__global__ void finalize(float* __restrict__ out) {
    const int i = blockIdx.x * 256 + threadIdx.x;
    const size_t base = (size_t)SS * BB * HH;
    out[base + i] = out[(size_t)(SS - 1) * BB * HH + i];   // h_t
    out[base + BB * HH + i] = g_c[0][i];                   // c_t (S even -> final in g_c[0])
}

// ---------------------------------------------------------------------------
extern "C" void kernel_launch(void* const* d_in, const int* in_sizes, int n_in,
                              void* d_out, int out_size) {
    (void)in_sizes; (void)n_in; (void)out_size;
    const float* x  = (const float*)d_in[0];
    const float* h0 = (const float*)d_in[1];
    const float* c0 = (const float*)d_in[2];
    const float* Ww = (const float*)d_in[3];
    const float* Wb = (const float*)d_in[4];
    const float* Uw = (const float*)d_in[5];
    float* out = (float*)d_out;

    copy_c0<<<(BB * HH) / 256, 256>>>(c0);

    gemm_xw<<<dim3(G4 / 64, (SS * BB) / 64), 256>>>(x, Ww, Wb);

    for (int t = 0; t < SS; t++) {
        const float* hp = (t == 0) ? h0 : (out + (size_t)(t - 1) * BB * HH);
        lstm_step<<<dim3(HH / 16, BB / 32), 128>>>(hp, Uw, t, t & 1,
                                                   out + (size_t)t * BB * HH);
    }

    finalize<<<(BB * HH) / 256, 256>>>(out);
}